// round 3
// baseline (speedup 1.0000x reference)
#include <cuda_runtime.h>
#include <cstdint>

#define N_NODES 100000
#define E_EDGES 1600000
#define NSEG    (2*N_NODES)
#define EN_TOT  (E_EDGES + N_NODES)
#define SCAN_BLOCKS ((NSEG + 1023) / 1024)

typedef unsigned long long ull;

// ---------------- device scratch (no runtime allocation) ----------------
static __device__ float4 g_h4  [N_NODES * 64];   // h both graphs: [n][256] floats
static __device__ float4 g_acc4[N_NODES * 64];   // relu(agg + bias), same layout
static __device__ float  g_asrc[N_NODES * 4];    // [n][graph*2+head]
static __device__ float  g_adst[N_NODES * 4];
static __device__ int    g_deg [NSEG];           // in-degree (incl self loop)
static __device__ int    g_off [NSEG + 1];       // CSR offsets
static __device__ int    g_cur [NSEG];           // placement cursors
static __device__ int    g_csr [2 * EN_TOT];     // src ids sorted by (graph,dst)
static __device__ int    g_part[256];            // scan partials

#define FFMA2(d, a, b) asm("fma.rn.f32x2 %0, %1, %2, %0;" : "+l"(d) : "l"(a), "l"(b))

__device__ __forceinline__ float f2lo(ull v) { return __uint_as_float((unsigned)v); }
__device__ __forceinline__ float f2hi(ull v) { return __uint_as_float((unsigned)(v >> 32)); }
__device__ __forceinline__ ull packf2(float lo, float hi) {
    return ((ull)__float_as_uint(hi) << 32) | (ull)__float_as_uint(lo);
}

// ---------------- deg init (self loop counts as 1) ----------------
__global__ void k_zero() {
    int i = blockIdx.x * blockDim.x + threadIdx.x;
    if (i < NSEG) g_deg[i] = 1;
}

// ---------------- GEMM 128x128 tiles, FFMA2, fused attention dots ----------------
__global__ void __launch_bounds__(256) k_gemm(
    const float* __restrict__ x,
    const float* __restrict__ W1, const float* __restrict__ W2,
    const float* __restrict__ as1, const float* __restrict__ ad1,
    const float* __restrict__ as2, const float* __restrict__ ad2)
{
    __shared__ float As [16][128];   // x tile, [k][row]
    __shared__ float Bs2[16][256];   // W tile, value-duplicated along cols
    __shared__ float satt_s[128], satt_d[128];

    const int g  = blockIdx.y;
    const float* W = g ? W2 : W1;
    const int n0 = blockIdx.x * 128;
    const int t  = threadIdx.x;
    const int tx = t & 15, ty = t >> 4;

    if (t < 128) {
        satt_s[t] = (g ? as2 : as1)[t];
        satt_d[t] = (g ? ad2 : ad1)[t];
    }

    ull acc2[4][8];
#pragma unroll
    for (int i = 0; i < 4; i++)
#pragma unroll
        for (int j = 0; j < 8; j++) acc2[i][j] = 0ull;

    for (int k0 = 0; k0 < 256; k0 += 16) {
#pragma unroll
        for (int i = 0; i < 2; i++) {
            int f = t + i * 256;
            int row = f >> 2, c4 = (f & 3) * 4;
            float4 v = make_float4(0.f, 0.f, 0.f, 0.f);
            if (n0 + row < N_NODES)
                v = *(const float4*)(x + (size_t)(n0 + row) * 256 + k0 + c4);
            As[c4 + 0][row] = v.x;
            As[c4 + 1][row] = v.y;
            As[c4 + 2][row] = v.z;
            As[c4 + 3][row] = v.w;
        }
#pragma unroll
        for (int i = 0; i < 2; i++) {
            int f = t + i * 256;
            int kk = f >> 5, c4 = (f & 31) * 4;
            float4 v = *(const float4*)(W + (size_t)(k0 + kk) * 128 + c4);
            *(float4*)&Bs2[kk][2 * c4]     = make_float4(v.x, v.x, v.y, v.y);
            *(float4*)&Bs2[kk][2 * c4 + 4] = make_float4(v.z, v.z, v.w, v.w);
        }
        __syncthreads();

#pragma unroll
        for (int kk = 0; kk < 16; kk++) {
            ulonglong2 a01 = *(const ulonglong2*)&As[kk][ty * 8];
            ulonglong2 a23 = *(const ulonglong2*)&As[kk][ty * 8 + 4];
            ull aa[4] = {a01.x, a01.y, a23.x, a23.y};
            ull bb[8];
#pragma unroll
            for (int jj = 0; jj < 8; jj++)
                bb[jj] = *(const ull*)&Bs2[kk][(tx + 16 * jj) * 2];
#pragma unroll
            for (int i2 = 0; i2 < 4; i2++)
#pragma unroll
                for (int jj = 0; jj < 8; jj++)
                    FFMA2(acc2[i2][jj], aa[i2], bb[jj]);
        }
        __syncthreads();
    }

    float* hbase = (float*)g_h4;
#pragma unroll
    for (int i2 = 0; i2 < 4; i2++) {
#pragma unroll
        for (int half = 0; half < 2; half++) {
            int row = n0 + ty * 8 + 2 * i2 + half;
            bool ok = row < N_NODES;
            float vv[8];
#pragma unroll
            for (int jj = 0; jj < 8; jj++)
                vv[jj] = half ? f2hi(acc2[i2][jj]) : f2lo(acc2[i2][jj]);
            float ds0 = 0.f, ds1 = 0.f, dd0 = 0.f, dd1 = 0.f;
#pragma unroll
            for (int jj = 0; jj < 8; jj++) {
                int col = tx + 16 * jj;
                if (ok) hbase[(size_t)row * 256 + g * 128 + col] = vv[jj];
                int ai = ((jj >> 2) << 6) + tx + (jj & 3) * 16;  // head*64 + (col&63)
                if (jj < 4) { ds0 = fmaf(vv[jj], satt_s[ai], ds0); dd0 = fmaf(vv[jj], satt_d[ai], dd0); }
                else        { ds1 = fmaf(vv[jj], satt_s[ai], ds1); dd1 = fmaf(vv[jj], satt_d[ai], dd1); }
            }
#pragma unroll
            for (int off = 8; off; off >>= 1) {
                ds0 += __shfl_down_sync(0xffffffffu, ds0, off, 16);
                ds1 += __shfl_down_sync(0xffffffffu, ds1, off, 16);
                dd0 += __shfl_down_sync(0xffffffffu, dd0, off, 16);
                dd1 += __shfl_down_sync(0xffffffffu, dd1, off, 16);
            }
            if (tx == 0 && ok) {
                int b = row * 4 + g * 2;
                g_asrc[b]     = ds0;
                g_asrc[b + 1] = ds1;
                g_adst[b]     = dd0;
                g_adst[b + 1] = dd1;
            }
        }
    }
}

// ---------------- degree histogram ----------------
__global__ void k_deg(const int* __restrict__ eic, const int* __restrict__ eil) {
    int i = blockIdx.x * blockDim.x + threadIdx.x;
    if (i >= E_EDGES) return;
    int g = blockIdx.y;
    const int* ei = g ? eil : eic;
    atomicAdd(&g_deg[g * N_NODES + ei[E_EDGES + i]], 1);
}

// ---------------- device-wide scan, pass 1: per-block sums (1024 elems/block) ----------------
__global__ void __launch_bounds__(256) k_scan1() {
    const int t = threadIdx.x;
    const int base = blockIdx.x * 1024 + t * 4;
    int s = 0;
#pragma unroll
    for (int j = 0; j < 4; j++) {
        int i = base + j;
        if (i < NSEG) s += g_deg[i];
    }
#pragma unroll
    for (int off = 16; off; off >>= 1)
        s += __shfl_down_sync(0xffffffffu, s, off);
    __shared__ int ws[8];
    if ((t & 31) == 0) ws[t >> 5] = s;
    __syncthreads();
    if (t == 0) {
        int tot = 0;
#pragma unroll
        for (int i = 0; i < 8; i++) tot += ws[i];
        g_part[blockIdx.x] = tot;
    }
}

// ---------------- pass 2: exclusive scan of partials (single small block) ----------------
__global__ void __launch_bounds__(256) k_scan2() {
    __shared__ int sh[256];
    const int t = threadIdx.x;
    int v = (t < SCAN_BLOCKS) ? g_part[t] : 0;
    sh[t] = v;
    __syncthreads();
#pragma unroll
    for (int off = 1; off < 256; off <<= 1) {
        int u = (t >= off) ? sh[t - off] : 0;
        __syncthreads();
        sh[t] += u;
        __syncthreads();
    }
    if (t < SCAN_BLOCKS) g_part[t] = (t == 0) ? 0 : sh[t - 1];
}

// ---------------- pass 3: per-block exclusive scan + base ----------------
__global__ void __launch_bounds__(256) k_scan3() {
    const int t = threadIdx.x;
    const int base = blockIdx.x * 1024 + t * 4;
    int v[4];
    int s = 0;
#pragma unroll
    for (int j = 0; j < 4; j++) {
        int i = base + j;
        v[j] = (i < NSEG) ? g_deg[i] : 0;
        s += v[j];
    }
    // warp inclusive scan of s
    int lane = t & 31, warp = t >> 5;
    int inc = s;
#pragma unroll
    for (int off = 1; off < 32; off <<= 1) {
        int u = __shfl_up_sync(0xffffffffu, inc, off);
        if (lane >= off) inc += u;
    }
    __shared__ int ws[8];
    if (lane == 31) ws[warp] = inc;
    __syncthreads();
    if (t < 8) {
        int u = ws[t];
        int iv = u;
#pragma unroll
        for (int off = 1; off < 8; off <<= 1) {
            int x2 = __shfl_up_sync(0xffu, iv, off, 8);
            if (t >= off) iv += x2;
        }
        ws[t] = iv - u;   // exclusive
    }
    __syncthreads();
    int excl = g_part[blockIdx.x] + ws[warp] + (inc - s);
#pragma unroll
    for (int j = 0; j < 4; j++) {
        int i = base + j;
        if (i < NSEG) {
            g_off[i] = excl;
            g_cur[i] = excl;
            excl += v[j];
        }
    }
    if (blockIdx.x == 0 && t == 0) g_off[NSEG] = 2 * EN_TOT;
}

// ---------------- CSR placement (edges + self loops) ----------------
__global__ void k_place(const int* __restrict__ eic, const int* __restrict__ eil) {
    int i = blockIdx.x * blockDim.x + threadIdx.x;
    if (i >= EN_TOT) return;
    int g = blockIdx.y;
    const int* ei = g ? eil : eic;
    int src, dst;
    if (i < E_EDGES) { src = ei[i]; dst = ei[E_EDGES + i]; }
    else             { src = dst = i - E_EDGES; }
    int pos = atomicAdd(&g_cur[g * N_NODES + dst], 1);
    g_csr[pos] = src;
}

// ---------------- gather: softmax (no max-sub) + aggregate + bias + relu ----------------
__global__ void __launch_bounds__(256) k_gather(
    const float* __restrict__ b1, const float* __restrict__ b2)
{
    int w = blockIdx.x * 8 + (threadIdx.x >> 5);
    int node = w >> 1, g = w & 1;
    if (node >= N_NODES) return;
    int lane = threadIdx.x & 31;
    int head = lane >> 4;

    int seg = g * N_NODES + node;
    int e   = g_off[seg];
    int end = g_off[seg + 1];
    float ad = g_adst[node * 4 + g * 2 + head];

    float4 acc = make_float4(0.f, 0.f, 0.f, 0.f);
    float ssum = 0.f;
    int src = g_csr[e];
    for (; e < end; e++) {
        int nsrc = (e + 1 < end) ? g_csr[e + 1] : 0;
        float as = g_asrc[src * 4 + g * 2 + head];
        float4 hv = g_h4[(size_t)src * 64 + g * 32 + lane];
        float ee = as + ad;
        ee = ee >= 0.f ? ee : 0.2f * ee;
        float p = __expf(ee);
        ssum += p;
        acc.x = fmaf(p, hv.x, acc.x);
        acc.y = fmaf(p, hv.y, acc.y);
        acc.z = fmaf(p, hv.z, acc.z);
        acc.w = fmaf(p, hv.w, acc.w);
        src = nsrc;
    }
    float r = 1.f / ssum;
    const float* bias = g ? b2 : b1;
    float4 bv = *(const float4*)(bias + lane * 4);
    float4 o;
    o.x = fmaxf(fmaf(acc.x, r, bv.x), 0.f);
    o.y = fmaxf(fmaf(acc.y, r, bv.y), 0.f);
    o.z = fmaxf(fmaf(acc.z, r, bv.z), 0.f);
    o.w = fmaxf(fmaf(acc.w, r, bv.w), 0.f);
    g_acc4[(size_t)node * 64 + g * 32 + lane] = o;
}

// ---------------- FC (concat already materialized), FFMA2 ----------------
__global__ void __launch_bounds__(256) k_fc(
    const float* __restrict__ fcW, const float* __restrict__ fcb,
    float* __restrict__ out)
{
    __shared__ float s2[16][512];   // duplicated activations
    const int n0 = blockIdx.x * 16;
    const int t  = threadIdx.x;
    const float* acc = (const float*)g_acc4;
#pragma unroll
    for (int i = 0; i < 16; i++) {
        float v = acc[(size_t)(n0 + i) * 256 + t];
        s2[i][2 * t]     = v;
        s2[i][2 * t + 1] = v;
    }
    __syncthreads();

    const int node = t >> 4;
    const int o4   = (t & 15) * 4;
    float4 bb = *(const float4*)(fcb + o4);
    ull a0 = packf2(bb.x, bb.y);
    ull a1 = packf2(bb.z, bb.w);
    const float* wp = fcW + o4;
#pragma unroll 8
    for (int k = 0; k < 256; k++) {
        ull sv = *(const ull*)&s2[node][2 * k];
        ulonglong2 wv = *(const ulonglong2*)(wp + (size_t)k * 64);
        FFMA2(a0, sv, wv.x);
        FFMA2(a1, sv, wv.y);
    }
    float4 o = make_float4(f2lo(a0), f2hi(a0), f2lo(a1), f2hi(a1));
    *(float4*)(out + (size_t)(n0 + node) * 64 + o4) = o;
}

// ---------------- launcher ----------------
extern "C" void kernel_launch(void* const* d_in, const int* in_sizes, int n_in,
                              void* d_out, int out_size) {
    const float* x   = (const float*)d_in[0];
    const int*   eic = (const int*)d_in[1];
    const int*   eil = (const int*)d_in[2];
    const float* W1  = (const float*)d_in[3];
    const float* as1 = (const float*)d_in[4];
    const float* ad1 = (const float*)d_in[5];
    const float* b1  = (const float*)d_in[6];
    const float* W2  = (const float*)d_in[7];
    const float* as2 = (const float*)d_in[8];
    const float* ad2 = (const float*)d_in[9];
    const float* b2  = (const float*)d_in[10];
    const float* fcW = (const float*)d_in[11];
    const float* fcb = (const float*)d_in[12];
    float* out = (float*)d_out;

    k_zero<<<(NSEG + 255) / 256, 256>>>();

    dim3 gg((N_NODES + 127) / 128, 2);
    k_gemm<<<gg, 256>>>(x, W1, W2, as1, ad1, as2, ad2);

    dim3 gd((E_EDGES + 255) / 256, 2);
    k_deg<<<gd, 256>>>(eic, eil);

    k_scan1<<<SCAN_BLOCKS, 256>>>();
    k_scan2<<<1, 256>>>();
    k_scan3<<<SCAN_BLOCKS, 256>>>();

    dim3 gp((EN_TOT + 255) / 256, 2);
    k_place<<<gp, 256>>>(eic, eil);

    k_gather<<<(2 * N_NODES + 7) / 8, 256>>>(b1, b2);

    k_fc<<<N_NODES / 16, 256>>>(fcW, fcb, out);
}

// round 4
// speedup vs baseline: 1.5780x; 1.5780x over previous
#include <cuda_runtime.h>
#include <cuda_fp16.h>
#include <cstdint>

#define N_NODES 100000
#define E_EDGES 1600000
#define NSEG    (2*N_NODES)
#define EN_TOT  (E_EDGES + N_NODES)
#define SCAN_BLOCKS ((NSEG + 1023) / 1024)

typedef unsigned long long ull;

// ---------------- device scratch (no runtime allocation) ----------------
static __device__ __half g_h16 [2 * N_NODES * 128]; // h, fp16, [g][node][128]
static __device__ float4 g_acc4[N_NODES * 64];      // relu(agg + bias), [n][256] floats
static __device__ float  g_asrc[N_NODES * 4];       // [n][graph*2+head]
static __device__ float  g_adst[N_NODES * 4];
static __device__ int    g_deg [NSEG];
static __device__ int    g_off [NSEG + 1];
static __device__ int    g_cur [NSEG];
static __device__ int    g_csr [2 * EN_TOT];
static __device__ int    g_part[256];

#define FFMA2(d, a, b) asm("fma.rn.f32x2 %0, %1, %2, %0;" : "+l"(d) : "l"(a), "l"(b))

__device__ __forceinline__ float f2lo(ull v) { return __uint_as_float((unsigned)v); }
__device__ __forceinline__ float f2hi(ull v) { return __uint_as_float((unsigned)(v >> 32)); }
__device__ __forceinline__ ull packf2(float lo, float hi) {
    return ((ull)__float_as_uint(hi) << 32) | (ull)__float_as_uint(lo);
}

// ---------------- deg init (self loop counts as 1) ----------------
__global__ void k_zero() {
    int i = blockIdx.x * blockDim.x + threadIdx.x;
    if (i < NSEG) g_deg[i] = 1;
}

// ---------------- GEMM 128x128 tiles, FFMA2, fused attention dots, fp16 h out ----------------
__global__ void __launch_bounds__(256) k_gemm(
    const float* __restrict__ x,
    const float* __restrict__ W1, const float* __restrict__ W2,
    const float* __restrict__ as1, const float* __restrict__ ad1,
    const float* __restrict__ as2, const float* __restrict__ ad2)
{
    __shared__ float As [16][128];   // x tile, [k][row]
    __shared__ float Bs2[16][256];   // W tile, value-duplicated along cols
    __shared__ float satt_s[128], satt_d[128];

    const int g  = blockIdx.y;
    const float* W = g ? W2 : W1;
    const int n0 = blockIdx.x * 128;
    const int t  = threadIdx.x;
    const int tx = t & 15, ty = t >> 4;

    if (t < 128) {
        satt_s[t] = (g ? as2 : as1)[t];
        satt_d[t] = (g ? ad2 : ad1)[t];
    }

    ull acc2[4][8];
#pragma unroll
    for (int i = 0; i < 4; i++)
#pragma unroll
        for (int j = 0; j < 8; j++) acc2[i][j] = 0ull;

    for (int k0 = 0; k0 < 256; k0 += 16) {
#pragma unroll
        for (int i = 0; i < 2; i++) {
            int f = t + i * 256;
            int row = f >> 2, c4 = (f & 3) * 4;
            float4 v = make_float4(0.f, 0.f, 0.f, 0.f);
            if (n0 + row < N_NODES)
                v = *(const float4*)(x + (size_t)(n0 + row) * 256 + k0 + c4);
            As[c4 + 0][row] = v.x;
            As[c4 + 1][row] = v.y;
            As[c4 + 2][row] = v.z;
            As[c4 + 3][row] = v.w;
        }
#pragma unroll
        for (int i = 0; i < 2; i++) {
            int f = t + i * 256;
            int kk = f >> 5, c4 = (f & 31) * 4;
            float4 v = *(const float4*)(W + (size_t)(k0 + kk) * 128 + c4);
            *(float4*)&Bs2[kk][2 * c4]     = make_float4(v.x, v.x, v.y, v.y);
            *(float4*)&Bs2[kk][2 * c4 + 4] = make_float4(v.z, v.z, v.w, v.w);
        }
        __syncthreads();

#pragma unroll
        for (int kk = 0; kk < 16; kk++) {
            ulonglong2 a01 = *(const ulonglong2*)&As[kk][ty * 8];
            ulonglong2 a23 = *(const ulonglong2*)&As[kk][ty * 8 + 4];
            ull aa[4] = {a01.x, a01.y, a23.x, a23.y};
            ull bb[8];
#pragma unroll
            for (int jj = 0; jj < 8; jj++)
                bb[jj] = *(const ull*)&Bs2[kk][(tx + 16 * jj) * 2];
#pragma unroll
            for (int i2 = 0; i2 < 4; i2++)
#pragma unroll
                for (int jj = 0; jj < 8; jj++)
                    FFMA2(acc2[i2][jj], aa[i2], bb[jj]);
        }
        __syncthreads();
    }

    __half* hbase = g_h16 + (size_t)g * N_NODES * 128;
#pragma unroll
    for (int i2 = 0; i2 < 4; i2++) {
#pragma unroll
        for (int half = 0; half < 2; half++) {
            int row = n0 + ty * 8 + 2 * i2 + half;
            bool ok = row < N_NODES;
            float vv[8];
#pragma unroll
            for (int jj = 0; jj < 8; jj++)
                vv[jj] = half ? f2hi(acc2[i2][jj]) : f2lo(acc2[i2][jj]);
            float ds0 = 0.f, ds1 = 0.f, dd0 = 0.f, dd1 = 0.f;
#pragma unroll
            for (int jj = 0; jj < 8; jj++) {
                int col = tx + 16 * jj;
                if (ok) hbase[(size_t)row * 128 + col] = __float2half(vv[jj]);
                int ai = ((jj >> 2) << 6) + tx + (jj & 3) * 16;  // head*64 + (col&63)
                if (jj < 4) { ds0 = fmaf(vv[jj], satt_s[ai], ds0); dd0 = fmaf(vv[jj], satt_d[ai], dd0); }
                else        { ds1 = fmaf(vv[jj], satt_s[ai], ds1); dd1 = fmaf(vv[jj], satt_d[ai], dd1); }
            }
#pragma unroll
            for (int off = 8; off; off >>= 1) {
                ds0 += __shfl_down_sync(0xffffffffu, ds0, off, 16);
                ds1 += __shfl_down_sync(0xffffffffu, ds1, off, 16);
                dd0 += __shfl_down_sync(0xffffffffu, dd0, off, 16);
                dd1 += __shfl_down_sync(0xffffffffu, dd1, off, 16);
            }
            if (tx == 0 && ok) {
                int b = row * 4 + g * 2;
                g_asrc[b]     = ds0;
                g_asrc[b + 1] = ds1;
                g_adst[b]     = dd0;
                g_adst[b + 1] = dd1;
            }
        }
    }
}

// ---------------- degree histogram ----------------
__global__ void k_deg(const int* __restrict__ eic, const int* __restrict__ eil) {
    int i = blockIdx.x * blockDim.x + threadIdx.x;
    if (i >= E_EDGES) return;
    int g = blockIdx.y;
    const int* ei = g ? eil : eic;
    atomicAdd(&g_deg[g * N_NODES + ei[E_EDGES + i]], 1);
}

// ---------------- device-wide scan (3 passes) ----------------
__global__ void __launch_bounds__(256) k_scan1() {
    const int t = threadIdx.x;
    const int base = blockIdx.x * 1024 + t * 4;
    int s = 0;
#pragma unroll
    for (int j = 0; j < 4; j++) {
        int i = base + j;
        if (i < NSEG) s += g_deg[i];
    }
#pragma unroll
    for (int off = 16; off; off >>= 1)
        s += __shfl_down_sync(0xffffffffu, s, off);
    __shared__ int ws[8];
    if ((t & 31) == 0) ws[t >> 5] = s;
    __syncthreads();
    if (t == 0) {
        int tot = 0;
#pragma unroll
        for (int i = 0; i < 8; i++) tot += ws[i];
        g_part[blockIdx.x] = tot;
    }
}

__global__ void __launch_bounds__(256) k_scan2() {
    __shared__ int sh[256];
    const int t = threadIdx.x;
    int v = (t < SCAN_BLOCKS) ? g_part[t] : 0;
    sh[t] = v;
    __syncthreads();
#pragma unroll
    for (int off = 1; off < 256; off <<= 1) {
        int u = (t >= off) ? sh[t - off] : 0;
        __syncthreads();
        sh[t] += u;
        __syncthreads();
    }
    if (t < SCAN_BLOCKS) g_part[t] = (t == 0) ? 0 : sh[t - 1];
}

__global__ void __launch_bounds__(256) k_scan3() {
    const int t = threadIdx.x;
    const int base = blockIdx.x * 1024 + t * 4;
    int v[4];
    int s = 0;
#pragma unroll
    for (int j = 0; j < 4; j++) {
        int i = base + j;
        v[j] = (i < NSEG) ? g_deg[i] : 0;
        s += v[j];
    }
    int lane = t & 31, warp = t >> 5;
    int inc = s;
#pragma unroll
    for (int off = 1; off < 32; off <<= 1) {
        int u = __shfl_up_sync(0xffffffffu, inc, off);
        if (lane >= off) inc += u;
    }
    __shared__ int ws[8];
    if (lane == 31) ws[warp] = inc;
    __syncthreads();
    if (t < 8) {
        int u = ws[t];
        int iv = u;
#pragma unroll
        for (int off = 1; off < 8; off <<= 1) {
            int x2 = __shfl_up_sync(0xffu, iv, off, 8);
            if (t >= off) iv += x2;
        }
        ws[t] = iv - u;
    }
    __syncthreads();
    int excl = g_part[blockIdx.x] + ws[warp] + (inc - s);
#pragma unroll
    for (int j = 0; j < 4; j++) {
        int i = base + j;
        if (i < NSEG) {
            g_off[i] = excl;
            g_cur[i] = excl;
            excl += v[j];
        }
    }
    if (blockIdx.x == 0 && t == 0) g_off[NSEG] = 2 * EN_TOT;
}

// ---------------- CSR placement (edges + self loops) ----------------
__global__ void k_place(const int* __restrict__ eic, const int* __restrict__ eil) {
    int i = blockIdx.x * blockDim.x + threadIdx.x;
    if (i >= EN_TOT) return;
    int g = blockIdx.y;
    const int* ei = g ? eil : eic;
    int src, dst;
    if (i < E_EDGES) { src = ei[i]; dst = ei[E_EDGES + i]; }
    else             { src = dst = i - E_EDGES; }
    int pos = atomicAdd(&g_cur[g * N_NODES + dst], 1);
    g_csr[pos] = src;
}

// ---------------- gather: softmax + aggregate + bias + relu (fp16 h, graph-major) --------
__global__ void __launch_bounds__(256) k_gather(
    const float* __restrict__ b1, const float* __restrict__ b2)
{
    int w = blockIdx.x * 8 + (threadIdx.x >> 5);      // graph-major: w in [0, 2N)
    if (w >= 2 * N_NODES) return;
    int g    = (w >= N_NODES) ? 1 : 0;
    int node = w - g * N_NODES;
    int lane = threadIdx.x & 31;
    int head = lane >> 4;

    int seg = g * N_NODES + node;
    int e   = g_off[seg];
    int end = g_off[seg + 1];
    float ad = g_adst[node * 4 + g * 2 + head];

    const __half* hg = g_h16 + (size_t)g * N_NODES * 128 + lane * 4;

    float4 acc = make_float4(0.f, 0.f, 0.f, 0.f);
    float ssum = 0.f;
    int src = g_csr[e];
    for (; e < end; e++) {
        int nsrc = (e + 1 < end) ? g_csr[e + 1] : 0;
        float as = g_asrc[src * 4 + g * 2 + head];
        uint2 hv = *(const uint2*)(hg + (size_t)src * 128);
        float ee = as + ad;
        ee = ee >= 0.f ? ee : 0.2f * ee;
        float p = __expf(ee);
        ssum += p;
        float2 f01 = __half22float2(*(const __half2*)&hv.x);
        float2 f23 = __half22float2(*(const __half2*)&hv.y);
        acc.x = fmaf(p, f01.x, acc.x);
        acc.y = fmaf(p, f01.y, acc.y);
        acc.z = fmaf(p, f23.x, acc.z);
        acc.w = fmaf(p, f23.y, acc.w);
        src = nsrc;
    }
    float r = 1.f / ssum;
    const float* bias = g ? b2 : b1;
    float4 bv = *(const float4*)(bias + lane * 4);
    float4 o;
    o.x = fmaxf(fmaf(acc.x, r, bv.x), 0.f);
    o.y = fmaxf(fmaf(acc.y, r, bv.y), 0.f);
    o.z = fmaxf(fmaf(acc.z, r, bv.z), 0.f);
    o.w = fmaxf(fmaf(acc.w, r, bv.w), 0.f);
    g_acc4[(size_t)node * 64 + g * 32 + lane] = o;
}

// ---------------- FC (concat already materialized), FFMA2 ----------------
__global__ void __launch_bounds__(256) k_fc(
    const float* __restrict__ fcW, const float* __restrict__ fcb,
    float* __restrict__ out)
{
    __shared__ float s2[16][512];   // duplicated activations
    const int n0 = blockIdx.x * 16;
    const int t  = threadIdx.x;
    const float* acc = (const float*)g_acc4;
#pragma unroll
    for (int i = 0; i < 16; i++) {
        float v = acc[(size_t)(n0 + i) * 256 + t];
        s2[i][2 * t]     = v;
        s2[i][2 * t + 1] = v;
    }
    __syncthreads();

    const int node = t >> 4;
    const int o4   = (t & 15) * 4;
    float4 bb = *(const float4*)(fcb + o4);
    ull a0 = packf2(bb.x, bb.y);
    ull a1 = packf2(bb.z, bb.w);
    const float* wp = fcW + o4;
#pragma unroll 8
    for (int k = 0; k < 256; k++) {
        ull sv = *(const ull*)&s2[node][2 * k];
        ulonglong2 wv = *(const ulonglong2*)(wp + (size_t)k * 64);
        FFMA2(a0, sv, wv.x);
        FFMA2(a1, sv, wv.y);
    }
    float4 o = make_float4(f2lo(a0), f2hi(a0), f2lo(a1), f2hi(a1));
    *(float4*)(out + (size_t)(n0 + node) * 64 + o4) = o;
}

// ---------------- launcher ----------------
extern "C" void kernel_launch(void* const* d_in, const int* in_sizes, int n_in,
                              void* d_out, int out_size) {
    const float* x   = (const float*)d_in[0];
    const int*   eic = (const int*)d_in[1];
    const int*   eil = (const int*)d_in[2];
    const float* W1  = (const float*)d_in[3];
    const float* as1 = (const float*)d_in[4];
    const float* ad1 = (const float*)d_in[5];
    const float* b1  = (const float*)d_in[6];
    const float* W2  = (const float*)d_in[7];
    const float* as2 = (const float*)d_in[8];
    const float* ad2 = (const float*)d_in[9];
    const float* b2  = (const float*)d_in[10];
    const float* fcW = (const float*)d_in[11];
    const float* fcb = (const float*)d_in[12];
    float* out = (float*)d_out;

    k_zero<<<(NSEG + 255) / 256, 256>>>();

    dim3 gg((N_NODES + 127) / 128, 2);
    k_gemm<<<gg, 256>>>(x, W1, W2, as1, ad1, as2, ad2);

    dim3 gd((E_EDGES + 255) / 256, 2);
    k_deg<<<gd, 256>>>(eic, eil);

    k_scan1<<<SCAN_BLOCKS, 256>>>();
    k_scan2<<<1, 256>>>();
    k_scan3<<<SCAN_BLOCKS, 256>>>();

    dim3 gp((EN_TOT + 255) / 256, 2);
    k_place<<<gp, 256>>>(eic, eil);

    k_gather<<<(2 * N_NODES + 7) / 8, 256>>>(b1, b2);

    k_fc<<<N_NODES / 16, 256>>>(fcW, fcb, out);
}